// round 2
// baseline (speedup 1.0000x reference)
#include <cuda_runtime.h>
#include <math.h>
#include <math_constants.h>

// ---------------- problem constants ----------------
#define B_    4
#define T_    1024
#define DM    2048
#define HD    64
#define NH    32
#define NKV   8
#define QMULT 4
#define WIN   128
#define QKVD  3072           // 64*(32+16)
#define SM_SCALE 0.125f      // 1/sqrt(64)
#define NTOK  (B_*T_)        // 4096

// ---------------- scratch (no allocs allowed) ----------------
__device__ float g_qkv [NTOK * QKVD];   // 50.3 MB
__device__ float g_attn[NTOK * DM];     // 33.6 MB
__device__ float g_cos [T_ * 32];
__device__ float g_sin [T_ * 32];

// ---------------- rope tables (YaRN / NTK-by-parts, gpt-oss) ----------------
__global__ void rope_table_kernel(float* __restrict__ cost, float* __restrict__ sint) {
    int t = blockIdx.x;      // 0..T-1
    int d = threadIdx.x;     // 0..31
    const double theta = 150000.0;
    const double two_pi = 6.283185307179586476925286766559;
    double freq = pow(theta, (double)d / 32.0);
    double concentration = 0.1 * log(32.0) + 1.0;
    double lt = log(theta);
    double low  = 32.0 * log(1024.0 / (32.0 * two_pi)) / lt;
    double high = 32.0 * log(1024.0 / (1.0  * two_pi)) / lt;
    double interpolation = 1.0 / (32.0 * freq);
    double extrapolation = 1.0 / freq;
    double ramp = ((double)d - low) / (high - low);
    ramp = fmin(fmax(ramp, 0.0), 1.0);
    // mask = 1 - ramp; inv = interp*(1-mask) + extrap*mask
    double inv_freq = interpolation * ramp + extrapolation * (1.0 - ramp);
    double a = (double)t * inv_freq;
    cost[t * 32 + d] = (float)(cos(a) * concentration);
    sint[t * 32 + d] = (float)(sin(a) * concentration);
}

// ---------------- rope apply (q heads 0..31, k heads 32..39), in place ----------------
__global__ void rope_apply_kernel(float* __restrict__ qkv,
                                  const float* __restrict__ cost,
                                  const float* __restrict__ sint) {
    int idx = blockIdx.x * blockDim.x + threadIdx.x;
    const int total = NTOK * 40 * 32;
    if (idx >= total) return;
    int d    = idx & 31;
    int head = (idx >> 5) % 40;          // 0..39 -> covers q(32) + k(8) heads
    int tok  = idx / (40 * 32);
    int t    = tok & (T_ - 1);
    float c = cost[t * 32 + d];
    float s = sint[t * 32 + d];
    float* p = qkv + (size_t)tok * QKVD + head * 64;
    float x1 = p[d];
    float x2 = p[d + 32];
    p[d]      = x1 * c - x2 * s;
    p[d + 32] = x2 * c + x1 * s;
}

// ---------------- SGEMM: C[M,N] = A[M,K] * B[N,K]^T + bias[N] ----------------
// Both operands K-major (row-major [M,K] and [N,K]). 128x128x16 tile, 8x8/thread.
__global__ __launch_bounds__(256) void sgemm_nt_bias(
    const float* __restrict__ A, const float* __restrict__ Bm,
    const float* __restrict__ bias, float* __restrict__ C,
    int M, int N, int K)
{
    __shared__ float As[16][132];
    __shared__ float Bs[16][132];

    const int tid = threadIdx.x;
    const int bm = blockIdx.y * 128;
    const int bn = blockIdx.x * 128;
    const int tx = tid & 15;
    const int ty = tid >> 4;
    const int lr = tid >> 2;         // 0..63 load row
    const int lc = (tid & 3) << 2;   // 0,4,8,12 load col

    const float* Ag = A  + (size_t)(bm + lr) * K + lc;
    const float* Bg = Bm + (size_t)(bn + lr) * K + lc;

    float acc[8][8];
    #pragma unroll
    for (int i = 0; i < 8; i++)
        #pragma unroll
        for (int j = 0; j < 8; j++) acc[i][j] = 0.0f;

    for (int k0 = 0; k0 < K; k0 += 16) {
        float4 av0 = *(const float4*)(Ag + k0);
        float4 av1 = *(const float4*)(Ag + (size_t)64 * K + k0);
        float4 bv0 = *(const float4*)(Bg + k0);
        float4 bv1 = *(const float4*)(Bg + (size_t)64 * K + k0);

        As[lc + 0][lr]      = av0.x; As[lc + 1][lr]      = av0.y;
        As[lc + 2][lr]      = av0.z; As[lc + 3][lr]      = av0.w;
        As[lc + 0][lr + 64] = av1.x; As[lc + 1][lr + 64] = av1.y;
        As[lc + 2][lr + 64] = av1.z; As[lc + 3][lr + 64] = av1.w;

        Bs[lc + 0][lr]      = bv0.x; Bs[lc + 1][lr]      = bv0.y;
        Bs[lc + 2][lr]      = bv0.z; Bs[lc + 3][lr]      = bv0.w;
        Bs[lc + 0][lr + 64] = bv1.x; Bs[lc + 1][lr + 64] = bv1.y;
        Bs[lc + 2][lr + 64] = bv1.z; Bs[lc + 3][lr + 64] = bv1.w;

        __syncthreads();

        #pragma unroll
        for (int kk = 0; kk < 16; kk++) {
            float4 a0 = *(const float4*)&As[kk][ty * 8];
            float4 a1 = *(const float4*)&As[kk][ty * 8 + 4];
            float4 b0 = *(const float4*)&Bs[kk][tx * 8];
            float4 b1 = *(const float4*)&Bs[kk][tx * 8 + 4];
            float ra[8] = {a0.x, a0.y, a0.z, a0.w, a1.x, a1.y, a1.z, a1.w};
            float rb[8] = {b0.x, b0.y, b0.z, b0.w, b1.x, b1.y, b1.z, b1.w};
            #pragma unroll
            for (int i = 0; i < 8; i++)
                #pragma unroll
                for (int j = 0; j < 8; j++)
                    acc[i][j] = fmaf(ra[i], rb[j], acc[i][j]);
        }
        __syncthreads();
    }

    #pragma unroll
    for (int i = 0; i < 8; i++) {
        float* Crow = C + (size_t)(bm + ty * 8 + i) * N + bn + tx * 8;
        #pragma unroll
        for (int j = 0; j < 8; j += 4) {
            float4 v;
            v.x = acc[i][j + 0] + bias[bn + tx * 8 + j + 0];
            v.y = acc[i][j + 1] + bias[bn + tx * 8 + j + 1];
            v.z = acc[i][j + 2] + bias[bn + tx * 8 + j + 2];
            v.w = acc[i][j + 3] + bias[bn + tx * 8 + j + 3];
            *(float4*)(Crow + j) = v;
        }
    }
}

// ---------------- attention: sliding-window causal GQA with sink ----------------
// grid: (T/64, NKV, B), block 256 = 4 q-heads x 64 queries.
// smem: K window tile [191][64] + V window tile [191][64] (fp32) = 97792 B.
__global__ __launch_bounds__(256) void attn_kernel(
    const float* __restrict__ qkv, const float* __restrict__ sinks,
    float* __restrict__ out)
{
    extern __shared__ float smem[];
    float* Ks = smem;
    float* Vs = smem + 191 * 64;

    const int qb = blockIdx.x;
    const int kv = blockIdx.y;
    const int b  = blockIdx.z;
    const int tid = threadIdx.x;

    const int qstart = qb * 64;
    const int j0 = qstart - (WIN - 1);   // first key in window union (may be < 0)

    // cooperative K/V tile load (191 rows x 64 cols, float4)
    for (int idx = tid; idx < 191 * 16; idx += 256) {
        int row = idx >> 4;
        int c   = (idx & 15) << 2;
        int j   = j0 + row;
        float4 kk4 = make_float4(0.f, 0.f, 0.f, 0.f);
        float4 vv4 = make_float4(0.f, 0.f, 0.f, 0.f);
        if (j >= 0) {
            const float* base = qkv + (size_t)(b * T_ + j) * QKVD;
            kk4 = *(const float4*)(base + 2048 + kv * 64 + c);
            vv4 = *(const float4*)(base + 2560 + kv * 64 + c);
        }
        *(float4*)(Ks + row * 64 + c) = kk4;
        *(float4*)(Vs + row * 64 + c) = vv4;
    }

    // this thread's query
    const int qi = tid & 63;
    const int qh = tid >> 6;                 // 0..3
    const int h  = kv * QMULT + qh;          // flat head 0..31
    const int i  = qstart + qi;              // global query pos

    float qv[64];
    {
        const float* qp = qkv + (size_t)(b * T_ + i) * QKVD + h * 64;
        #pragma unroll
        for (int d = 0; d < 64; d += 4) {
            float4 t4 = *(const float4*)(qp + d);
            qv[d] = t4.x; qv[d + 1] = t4.y; qv[d + 2] = t4.z; qv[d + 3] = t4.w;
        }
    }

    __syncthreads();

    float m = -CUDART_INF_F;
    float l = 0.0f;
    float o[64];
    #pragma unroll
    for (int d = 0; d < 64; d++) o[d] = 0.0f;

    for (int jr = 0; jr < 191; jr++) {
        int j = j0 + jr;
        // valid window for query i: jr in [qi, qi+127], and j >= 0
        bool valid = (jr >= qi) && (jr <= qi + (WIN - 1)) && (j >= 0);
        if (valid) {
            const float* kr = Ks + jr * 64;
            float s0 = 0.f, s1 = 0.f, s2 = 0.f, s3 = 0.f;
            #pragma unroll
            for (int d = 0; d < 64; d += 4) {
                float4 k4 = *(const float4*)(kr + d);
                s0 = fmaf(qv[d + 0], k4.x, s0);
                s1 = fmaf(qv[d + 1], k4.y, s1);
                s2 = fmaf(qv[d + 2], k4.z, s2);
                s3 = fmaf(qv[d + 3], k4.w, s3);
            }
            float s = ((s0 + s1) + (s2 + s3)) * SM_SCALE;
            if (s > m) {
                float corr = __expf(m - s);   // m == -inf first time -> 0
                l *= corr;
                #pragma unroll
                for (int d = 0; d < 64; d++) o[d] *= corr;
                m = s;
            }
            float p = __expf(s - m);
            l += p;
            const float* vr = Vs + jr * 64;
            #pragma unroll
            for (int d = 0; d < 64; d += 4) {
                float4 v4 = *(const float4*)(vr + d);
                o[d + 0] = fmaf(p, v4.x, o[d + 0]);
                o[d + 1] = fmaf(p, v4.y, o[d + 1]);
                o[d + 2] = fmaf(p, v4.z, o[d + 2]);
                o[d + 3] = fmaf(p, v4.w, o[d + 3]);
            }
        }
    }

    float denom = l + __expf(sinks[h] - m);   // sink folded into denominator
    float inv = 1.0f / denom;
    float* op = out + (size_t)(b * T_ + i) * DM + h * 64;
    #pragma unroll
    for (int d = 0; d < 64; d += 4) {
        float4 v4;
        v4.x = o[d + 0] * inv; v4.y = o[d + 1] * inv;
        v4.z = o[d + 2] * inv; v4.w = o[d + 3] * inv;
        *(float4*)(op + d) = v4;
    }
}

// ---------------- launch ----------------
extern "C" void kernel_launch(void* const* d_in, const int* in_sizes, int n_in,
                              void* d_out, int out_size) {
    const float* x      = (const float*)d_in[0];
    const float* qkv_w  = (const float*)d_in[1];
    const float* qkv_b  = (const float*)d_in[2];
    const float* out_w  = (const float*)d_in[3];
    const float* out_b  = (const float*)d_in[4];
    const float* sinks  = (const float*)d_in[5];
    float* out = (float*)d_out;

    float *qkv, *attn, *cosp, *sinp;
    cudaGetSymbolAddress((void**)&qkv,  g_qkv);
    cudaGetSymbolAddress((void**)&attn, g_attn);
    cudaGetSymbolAddress((void**)&cosp, g_cos);
    cudaGetSymbolAddress((void**)&sinp, g_sin);

    // 1. rope tables
    rope_table_kernel<<<T_, 32>>>(cosp, sinp);

    // 2. QKV projection: [4096,3072] = x[4096,2048] @ qkv_w[3072,2048]^T + b
    {
        dim3 grid(QKVD / 128, NTOK / 128);
        sgemm_nt_bias<<<grid, 256>>>(x, qkv_w, qkv_b, qkv, NTOK, QKVD, DM);
    }

    // 3. rope on q + k heads (in place)
    {
        int total = NTOK * 40 * 32;
        rope_apply_kernel<<<(total + 255) / 256, 256>>>(qkv, cosp, sinp);
    }

    // 4. attention
    {
        cudaFuncSetAttribute(attn_kernel, cudaFuncAttributeMaxDynamicSharedMemorySize, 98304);
        dim3 grid(T_ / 64, NKV, B_);
        attn_kernel<<<grid, 256, 191 * 64 * 2 * sizeof(float)>>>(qkv, sinks, attn);
    }

    // 5. output projection: [4096,2048] = attn @ out_w[2048,2048]^T + b
    {
        dim3 grid(DM / 128, NTOK / 128);
        sgemm_nt_bias<<<grid, 256>>>(attn, out_w, out_b, out, NTOK, DM, DM);
    }
}

// round 3
// speedup vs baseline: 1.6343x; 1.6343x over previous
#include <cuda_runtime.h>
#include <math.h>
#include <math_constants.h>

// ---------------- problem constants ----------------
#define B_    4
#define T_    1024
#define DM    2048
#define HD    64
#define NH    32
#define NKV   8
#define QMULT 4
#define WIN   128
#define QKVD  3072           // 64*(32+16)
#define SM_SCALE 0.125f      // 1/sqrt(64)
#define NTOK  (B_*T_)        // 4096

// ---------------- scratch (no allocs allowed) ----------------
__device__ float g_qkv [NTOK * QKVD];   // 50.3 MB
__device__ float g_attn[NTOK * DM];     // 33.6 MB
__device__ float g_cos [T_ * 32];
__device__ float g_sin [T_ * 32];

// ---------------- rope tables (YaRN / NTK-by-parts, gpt-oss) ----------------
__global__ void rope_table_kernel(float* __restrict__ cost, float* __restrict__ sint) {
    int t = blockIdx.x;      // 0..T-1
    int d = threadIdx.x;     // 0..31
    const double theta = 150000.0;
    const double two_pi = 6.283185307179586476925286766559;
    double freq = pow(theta, (double)d / 32.0);
    double concentration = 0.1 * log(32.0) + 1.0;
    double lt = log(theta);
    double low  = 32.0 * log(1024.0 / (32.0 * two_pi)) / lt;
    double high = 32.0 * log(1024.0 / (1.0  * two_pi)) / lt;
    double interpolation = 1.0 / (32.0 * freq);
    double extrapolation = 1.0 / freq;
    double ramp = ((double)d - low) / (high - low);
    ramp = fmin(fmax(ramp, 0.0), 1.0);
    double inv_freq = interpolation * ramp + extrapolation * (1.0 - ramp);
    double a = (double)t * inv_freq;
    cost[t * 32 + d] = (float)(cos(a) * concentration);
    sint[t * 32 + d] = (float)(sin(a) * concentration);
}

// ---------------- rope apply (q heads 0..31, k heads 32..39), in place ----------------
__global__ void rope_apply_kernel(float* __restrict__ qkv,
                                  const float* __restrict__ cost,
                                  const float* __restrict__ sint) {
    int idx = blockIdx.x * blockDim.x + threadIdx.x;
    const int total = NTOK * 40 * 32;
    if (idx >= total) return;
    int d    = idx & 31;
    int head = (idx >> 5) % 40;
    int tok  = idx / (40 * 32);
    int t    = tok & (T_ - 1);
    float c = cost[t * 32 + d];
    float s = sint[t * 32 + d];
    float* p = qkv + (size_t)tok * QKVD + head * 64;
    float x1 = p[d];
    float x2 = p[d + 32];
    p[d]      = x1 * c - x2 * s;
    p[d + 32] = x2 * c + x1 * s;
}

// ---------------- TF32 tensor-core GEMM: C[M,N] = A[M,K] @ B[N,K]^T + bias ----------------
// 128x128x32 CTA tile, 8 warps (2m x 4n), each warp 64x32 via m16n8k8 tf32 mma.
// Double-buffered smem, register prefetch, 1 sync per K-iter.
#define BM 128
#define BN 128
#define BK 32
#define BKP 36   // padded row stride (uint32) -> conflict-free fragment loads

__device__ __forceinline__ unsigned f2tf32(float x) {
    unsigned y;
    asm("cvt.rna.tf32.f32 %0, %1;" : "=r"(y) : "f"(x));
    return y;
}

__device__ __forceinline__ void mma_tf32(float* c, const unsigned* a, const unsigned* b) {
    asm volatile(
        "mma.sync.aligned.m16n8k8.row.col.f32.tf32.tf32.f32 "
        "{%0,%1,%2,%3}, {%4,%5,%6,%7}, {%8,%9}, {%0,%1,%2,%3};\n"
        : "+f"(c[0]), "+f"(c[1]), "+f"(c[2]), "+f"(c[3])
        : "r"(a[0]), "r"(a[1]), "r"(a[2]), "r"(a[3]), "r"(b[0]), "r"(b[1]));
}

__global__ __launch_bounds__(256) void gemm_tf32_nt_bias(
    const float* __restrict__ A, const float* __restrict__ Bm,
    const float* __restrict__ bias, float* __restrict__ C,
    int M, int N, int K)
{
    extern __shared__ unsigned sm_[];
    unsigned* Abuf[2] = { sm_,                sm_ + 2 * BM * BKP };
    unsigned* Bbuf[2] = { sm_ + BM * BKP,     sm_ + 3 * BM * BKP };

    const int tid  = threadIdx.x;
    const int lane = tid & 31;
    const int wid  = tid >> 5;
    const int wm   = wid >> 2;          // 0..1 -> m base wm*64
    const int wn   = wid & 3;           // 0..3 -> n base wn*32
    const int bm   = blockIdx.y * BM;
    const int bn   = blockIdx.x * BN;

    const int rA = tid >> 3;            // 0..31
    const int cA = (tid & 7) << 2;      // 0,4,...,28

    const float* Ag = A  + (size_t)(bm + rA) * K + cA;
    const float* Bg = Bm + (size_t)(bn + rA) * K + cA;

    float acc[4][4][4];
    #pragma unroll
    for (int i = 0; i < 4; i++)
        #pragma unroll
        for (int j = 0; j < 4; j++)
            #pragma unroll
            for (int r = 0; r < 4; r++) acc[i][j][r] = 0.0f;

    const int kIter = K / BK;

    // first tile -> buf 0
    {
        #pragma unroll
        for (int f = 0; f < 4; f++) {
            float4 a4 = *(const float4*)(Ag + (size_t)(f * 32) * K);
            float4 b4 = *(const float4*)(Bg + (size_t)(f * 32) * K);
            unsigned* as = Abuf[0] + (f * 32 + rA) * BKP + cA;
            unsigned* bs = Bbuf[0] + (f * 32 + rA) * BKP + cA;
            as[0] = f2tf32(a4.x); as[1] = f2tf32(a4.y); as[2] = f2tf32(a4.z); as[3] = f2tf32(a4.w);
            bs[0] = f2tf32(b4.x); bs[1] = f2tf32(b4.y); bs[2] = f2tf32(b4.z); bs[3] = f2tf32(b4.w);
        }
    }
    __syncthreads();

    const int gid = lane >> 2;          // 0..7
    const int tig = lane & 3;           // 0..3

    for (int t = 0; t < kIter; t++) {
        // prefetch next tile into regs (redundant reload of tile 0 on last iter)
        int tn = (t + 1 < kIter) ? (t + 1) : 0;
        float4 pa[4], pb[4];
        #pragma unroll
        for (int f = 0; f < 4; f++) {
            pa[f] = *(const float4*)(Ag + (size_t)(f * 32) * K + tn * BK);
            pb[f] = *(const float4*)(Bg + (size_t)(f * 32) * K + tn * BK);
        }

        // compute on current buffer
        const unsigned* As = Abuf[t & 1];
        const unsigned* Bs = Bbuf[t & 1];
        #pragma unroll
        for (int ks = 0; ks < 4; ks++) {
            const int k0 = ks * 8;
            unsigned af[4][4];
            #pragma unroll
            for (int mt = 0; mt < 4; mt++) {
                const unsigned* ap = As + (wm * 64 + mt * 16 + gid) * BKP + k0 + tig;
                af[mt][0] = ap[0];
                af[mt][1] = ap[8 * BKP];
                af[mt][2] = ap[4];
                af[mt][3] = ap[8 * BKP + 4];
            }
            unsigned bf[4][2];
            #pragma unroll
            for (int nt = 0; nt < 4; nt++) {
                const unsigned* bp = Bs + (wn * 32 + nt * 8 + gid) * BKP + k0 + tig;
                bf[nt][0] = bp[0];
                bf[nt][1] = bp[4];
            }
            #pragma unroll
            for (int mt = 0; mt < 4; mt++)
                #pragma unroll
                for (int nt = 0; nt < 4; nt++)
                    mma_tf32(acc[mt][nt], af[mt], bf[nt]);
        }

        // store prefetched tile into the other buffer (safe: nobody reads it yet)
        unsigned* An = Abuf[(t + 1) & 1];
        unsigned* Bn = Bbuf[(t + 1) & 1];
        #pragma unroll
        for (int f = 0; f < 4; f++) {
            unsigned* as = An + (f * 32 + rA) * BKP + cA;
            unsigned* bs = Bn + (f * 32 + rA) * BKP + cA;
            as[0] = f2tf32(pa[f].x); as[1] = f2tf32(pa[f].y); as[2] = f2tf32(pa[f].z); as[3] = f2tf32(pa[f].w);
            bs[0] = f2tf32(pb[f].x); bs[1] = f2tf32(pb[f].y); bs[2] = f2tf32(pb[f].z); bs[3] = f2tf32(pb[f].w);
        }
        __syncthreads();
    }

    // epilogue: acc + bias -> C
    #pragma unroll
    for (int nt = 0; nt < 4; nt++) {
        const int c0 = bn + wn * 32 + nt * 8 + tig * 2;
        const float bv0 = bias[c0];
        const float bv1 = bias[c0 + 1];
        #pragma unroll
        for (int mt = 0; mt < 4; mt++) {
            const int r0 = bm + wm * 64 + mt * 16 + gid;
            float2 v0 = make_float2(acc[mt][nt][0] + bv0, acc[mt][nt][1] + bv1);
            float2 v1 = make_float2(acc[mt][nt][2] + bv0, acc[mt][nt][3] + bv1);
            *(float2*)(C + (size_t)r0 * N + c0)       = v0;
            *(float2*)(C + (size_t)(r0 + 8) * N + c0) = v1;
        }
    }
}

// ---------------- attention: sliding-window causal GQA with sink ----------------
__global__ __launch_bounds__(256) void attn_kernel(
    const float* __restrict__ qkv, const float* __restrict__ sinks,
    float* __restrict__ out)
{
    extern __shared__ float smem[];
    float* Ks = smem;
    float* Vs = smem + 191 * 64;

    const int qb = blockIdx.x;
    const int kv = blockIdx.y;
    const int b  = blockIdx.z;
    const int tid = threadIdx.x;

    const int qstart = qb * 64;
    const int j0 = qstart - (WIN - 1);

    for (int idx = tid; idx < 191 * 16; idx += 256) {
        int row = idx >> 4;
        int c   = (idx & 15) << 2;
        int j   = j0 + row;
        float4 kk4 = make_float4(0.f, 0.f, 0.f, 0.f);
        float4 vv4 = make_float4(0.f, 0.f, 0.f, 0.f);
        if (j >= 0) {
            const float* base = qkv + (size_t)(b * T_ + j) * QKVD;
            kk4 = *(const float4*)(base + 2048 + kv * 64 + c);
            vv4 = *(const float4*)(base + 2560 + kv * 64 + c);
        }
        *(float4*)(Ks + row * 64 + c) = kk4;
        *(float4*)(Vs + row * 64 + c) = vv4;
    }

    const int qi = tid & 63;
    const int qh = tid >> 6;
    const int h  = kv * QMULT + qh;
    const int i  = qstart + qi;

    float qv[64];
    {
        const float* qp = qkv + (size_t)(b * T_ + i) * QKVD + h * 64;
        #pragma unroll
        for (int d = 0; d < 64; d += 4) {
            float4 t4 = *(const float4*)(qp + d);
            qv[d] = t4.x; qv[d + 1] = t4.y; qv[d + 2] = t4.z; qv[d + 3] = t4.w;
        }
    }

    __syncthreads();

    float m = -CUDART_INF_F;
    float l = 0.0f;
    float o[64];
    #pragma unroll
    for (int d = 0; d < 64; d++) o[d] = 0.0f;

    for (int jr = 0; jr < 191; jr++) {
        int j = j0 + jr;
        bool valid = (jr >= qi) && (jr <= qi + (WIN - 1)) && (j >= 0);
        if (valid) {
            const float* kr = Ks + jr * 64;
            float s0 = 0.f, s1 = 0.f, s2 = 0.f, s3 = 0.f;
            #pragma unroll
            for (int d = 0; d < 64; d += 4) {
                float4 k4 = *(const float4*)(kr + d);
                s0 = fmaf(qv[d + 0], k4.x, s0);
                s1 = fmaf(qv[d + 1], k4.y, s1);
                s2 = fmaf(qv[d + 2], k4.z, s2);
                s3 = fmaf(qv[d + 3], k4.w, s3);
            }
            float s = ((s0 + s1) + (s2 + s3)) * SM_SCALE;
            if (s > m) {
                float corr = __expf(m - s);
                l *= corr;
                #pragma unroll
                for (int d = 0; d < 64; d++) o[d] *= corr;
                m = s;
            }
            float p = __expf(s - m);
            l += p;
            const float* vr = Vs + jr * 64;
            #pragma unroll
            for (int d = 0; d < 64; d += 4) {
                float4 v4 = *(const float4*)(vr + d);
                o[d + 0] = fmaf(p, v4.x, o[d + 0]);
                o[d + 1] = fmaf(p, v4.y, o[d + 1]);
                o[d + 2] = fmaf(p, v4.z, o[d + 2]);
                o[d + 3] = fmaf(p, v4.w, o[d + 3]);
            }
        }
    }

    float denom = l + __expf(sinks[h] - m);
    float inv = 1.0f / denom;
    float* op = out + (size_t)(b * T_ + i) * DM + h * 64;
    #pragma unroll
    for (int d = 0; d < 64; d += 4) {
        float4 v4;
        v4.x = o[d + 0] * inv; v4.y = o[d + 1] * inv;
        v4.z = o[d + 2] * inv; v4.w = o[d + 3] * inv;
        *(float4*)(op + d) = v4;
    }
}

// ---------------- launch ----------------
extern "C" void kernel_launch(void* const* d_in, const int* in_sizes, int n_in,
                              void* d_out, int out_size) {
    const float* x      = (const float*)d_in[0];
    const float* qkv_w  = (const float*)d_in[1];
    const float* qkv_b  = (const float*)d_in[2];
    const float* out_w  = (const float*)d_in[3];
    const float* out_b  = (const float*)d_in[4];
    const float* sinks  = (const float*)d_in[5];
    float* out = (float*)d_out;

    float *qkv, *attn, *cosp, *sinp;
    cudaGetSymbolAddress((void**)&qkv,  g_qkv);
    cudaGetSymbolAddress((void**)&attn, g_attn);
    cudaGetSymbolAddress((void**)&cosp, g_cos);
    cudaGetSymbolAddress((void**)&sinp, g_sin);

    const int gemmSmem = 4 * BM * BKP * 4;   // 73728 B
    cudaFuncSetAttribute(gemm_tf32_nt_bias, cudaFuncAttributeMaxDynamicSharedMemorySize, gemmSmem);

    // 1. rope tables
    rope_table_kernel<<<T_, 32>>>(cosp, sinp);

    // 2. QKV projection: [4096,3072] = x @ qkv_w^T + b
    {
        dim3 grid(QKVD / BN, NTOK / BM);
        gemm_tf32_nt_bias<<<grid, 256, gemmSmem>>>(x, qkv_w, qkv_b, qkv, NTOK, QKVD, DM);
    }

    // 3. rope on q + k heads (in place)
    {
        int total = NTOK * 40 * 32;
        rope_apply_kernel<<<(total + 255) / 256, 256>>>(qkv, cosp, sinp);
    }

    // 4. attention
    {
        cudaFuncSetAttribute(attn_kernel, cudaFuncAttributeMaxDynamicSharedMemorySize, 98304);
        dim3 grid(T_ / 64, NKV, B_);
        attn_kernel<<<grid, 256, 191 * 64 * 2 * sizeof(float)>>>(qkv, sinks, attn);
    }

    // 5. output projection: [4096,2048] = attn @ out_w^T + b
    {
        dim3 grid(DM / BN, NTOK / BM);
        gemm_tf32_nt_bias<<<grid, 256, gemmSmem>>>(attn, out_w, out_b, out, NTOK, DM, DM);
    }
}

// round 5
// speedup vs baseline: 2.8169x; 1.7236x over previous
#include <cuda_runtime.h>
#include <cuda_fp16.h>
#include <math.h>
#include <math_constants.h>
#include <stdint.h>

// ---------------- problem constants ----------------
#define B_    4
#define T_    1024
#define DM    2048
#define HD    64
#define NH    32
#define NKV   8
#define QMULT 4
#define WIN   128
#define QKVD  3072           // 64*(32+16)
#define SM_SCALE 0.125f      // 1/sqrt(64)
#define NTOK  (B_*T_)        // 4096

// ---------------- scratch (no allocs allowed) ----------------
__device__ float  g_qkv  [NTOK * QKVD];  // 50.3 MB  qkv projection output (fp32)
__device__ __half g_xh   [NTOK * DM];    // 16.8 MB  x -> fp16
__device__ __half g_qwh  [QKVD * DM];    // 12.6 MB  qkv_w -> fp16
__device__ __half g_owh  [DM * DM];      //  8.4 MB  out_w -> fp16
__device__ __half g_attnh[NTOK * DM];    //  16.8 MB attn output (fp16)
__device__ float  g_cos  [T_ * 32];
__device__ float  g_sin  [T_ * 32];

// ---------------- PTX helpers ----------------
__device__ __forceinline__ uint32_t smem_u32(const void* p) {
    uint32_t a;
    asm("{ .reg .u64 t; cvta.to.shared.u64 t, %1; cvt.u32.u64 %0, t; }" : "=r"(a) : "l"(p));
    return a;
}
__device__ __forceinline__ void cp16(uint32_t dst, const void* src) {
    asm volatile("cp.async.cg.shared.global [%0], [%1], 16;" :: "r"(dst), "l"(src));
}
__device__ __forceinline__ void ldsm_x4(uint32_t& r0, uint32_t& r1, uint32_t& r2, uint32_t& r3, uint32_t addr) {
    asm volatile("ldmatrix.sync.aligned.m8n8.x4.shared.b16 {%0,%1,%2,%3}, [%4];"
        : "=r"(r0), "=r"(r1), "=r"(r2), "=r"(r3) : "r"(addr));
}
__device__ __forceinline__ void mma_f16(float* c, const uint32_t* a, const uint32_t* b) {
    asm volatile("mma.sync.aligned.m16n8k16.row.col.f32.f16.f16.f32 "
        "{%0,%1,%2,%3}, {%4,%5,%6,%7}, {%8,%9}, {%0,%1,%2,%3};"
        : "+f"(c[0]), "+f"(c[1]), "+f"(c[2]), "+f"(c[3])
        : "r"(a[0]), "r"(a[1]), "r"(a[2]), "r"(a[3]), "r"(b[0]), "r"(b[1]));
}

// ---------------- rope tables (YaRN / NTK-by-parts) ----------------
__global__ void rope_table_kernel(float* __restrict__ cost, float* __restrict__ sint) {
    int t = blockIdx.x;
    int d = threadIdx.x;
    const double theta = 150000.0;
    const double two_pi = 6.283185307179586476925286766559;
    double freq = pow(theta, (double)d / 32.0);
    double concentration = 0.1 * log(32.0) + 1.0;
    double lt = log(theta);
    double low  = 32.0 * log(1024.0 / (32.0 * two_pi)) / lt;
    double high = 32.0 * log(1024.0 / (1.0  * two_pi)) / lt;
    double interpolation = 1.0 / (32.0 * freq);
    double extrapolation = 1.0 / freq;
    double ramp = ((double)d - low) / (high - low);
    ramp = fmin(fmax(ramp, 0.0), 1.0);
    double inv_freq = interpolation * ramp + extrapolation * (1.0 - ramp);
    double a = (double)t * inv_freq;
    cost[t * 32 + d] = (float)(cos(a) * concentration);
    sint[t * 32 + d] = (float)(sin(a) * concentration);
}

// ---------------- rope apply (q heads 0..31, k heads 32..39), in place fp32 ----------------
__global__ void rope_apply_kernel(float* __restrict__ qkv,
                                  const float* __restrict__ cost,
                                  const float* __restrict__ sint) {
    int idx = blockIdx.x * blockDim.x + threadIdx.x;
    const int total = NTOK * 40 * 32;
    if (idx >= total) return;
    int d    = idx & 31;
    int head = (idx >> 5) % 40;
    int tok  = idx / (40 * 32);
    int t    = tok & (T_ - 1);
    float c = cost[t * 32 + d];
    float s = sint[t * 32 + d];
    float* p = qkv + (size_t)tok * QKVD + head * 64;
    float x1 = p[d];
    float x2 = p[d + 32];
    p[d]      = x1 * c - x2 * s;
    p[d + 32] = x2 * c + x1 * s;
}

// ---------------- fp32 -> fp16 conversion ----------------
__global__ void f16_convert_kernel(const float* __restrict__ in, __half* __restrict__ out, int n4) {
    int i = blockIdx.x * blockDim.x + threadIdx.x;
    if (i >= n4) return;
    float4 v = ((const float4*)in)[i];
    __half2* o2 = (__half2*)out;
    o2[2 * i]     = __floats2half2_rn(v.x, v.y);
    o2[2 * i + 1] = __floats2half2_rn(v.z, v.w);
}

// ---------------- fp16 tensor-core GEMM: C[M,N] = A[M,K] @ B[N,K]^T + bias ----------------
// 128x128 CTA tile, BK=64 (128B rows, SW128 swizzle), cp.async double buffer,
// ldmatrix fragment loads, m16n8k16 fp16 mma with fp32 accum.
#define BM 128
#define BN 128
#define BK 64
#define STAGE_BYTES 32768    // A(16KB) + B(16KB) per stage

__global__ __launch_bounds__(256) void gemm_f16_nt_bias(
    const __half* __restrict__ A, const __half* __restrict__ Bw,
    const float* __restrict__ bias, float* __restrict__ C,
    int M, int N, int K)
{
    extern __shared__ char dsm[];
    const uint32_t dynbase = smem_u32(dsm);
    const uint32_t base    = (dynbase + 1023u) & ~1023u;

    const int tid  = threadIdx.x;
    const int lane = tid & 31;
    const int wid  = tid >> 5;
    const int wm   = wid >> 2;          // 0..1 -> m base wm*64
    const int wn   = wid & 3;           // 0..3 -> n base wn*32
    const int bm   = blockIdx.y * BM;
    const int bn   = blockIdx.x * BN;

    const int lr = tid >> 1;            // 0..127 load row
    const int lc = tid & 1;             // chunk pair selector

    float acc[4][4][4];
    #pragma unroll
    for (int i = 0; i < 4; i++)
        #pragma unroll
        for (int j = 0; j < 4; j++)
            #pragma unroll
            for (int r = 0; r < 4; r++) acc[i][j][r] = 0.0f;

    const int kIter = K / BK;

    // ---- stage loader: 128 rows x 64 fp16 (=8 x 16B chunks/row) for A and B ----
    auto load_stage = [&](int buf, int t) {
        const uint32_t aS = base + buf * STAGE_BYTES;
        const uint32_t bS = aS + 16384;
        const __half* Ab = A  + (size_t)(bm + lr) * K + (size_t)t * BK;
        const __half* Bb = Bw + (size_t)(bn + lr) * K + (size_t)t * BK;
        #pragma unroll
        for (int j = 0; j < 4; j++) {
            int c = lc * 4 + j;                       // 0..7 chunk
            uint32_t off = (uint32_t)(lr * 128 + c * 16);
            uint32_t sw  = off ^ ((off >> 3) & 0x70);
            cp16(aS + sw, Ab + c * 8);
            cp16(bS + sw, Bb + c * 8);
        }
    };

    load_stage(0, 0);
    asm volatile("cp.async.commit_group;");

    for (int t = 0; t < kIter; t++) {
        if (t + 1 < kIter) load_stage((t + 1) & 1, t + 1);
        asm volatile("cp.async.commit_group;");
        asm volatile("cp.async.wait_group 1;");
        __syncthreads();

        const uint32_t aS = base + (t & 1) * STAGE_BYTES;
        const uint32_t bS = aS + 16384;
        const int rsel = lane & 15;
        const int hsel = (lane >> 4) & 1;

        #pragma unroll
        for (int ks = 0; ks < 4; ks++) {
            uint32_t af[4][4];
            #pragma unroll
            for (int mt = 0; mt < 4; mt++) {
                int row = wm * 64 + mt * 16 + rsel;
                uint32_t off = (uint32_t)(row * 128 + ks * 32 + hsel * 16);
                uint32_t sw  = off ^ ((off >> 3) & 0x70);
                ldsm_x4(af[mt][0], af[mt][1], af[mt][2], af[mt][3], aS + sw);
            }
            uint32_t bf[4][2];
            #pragma unroll
            for (int np = 0; np < 2; np++) {
                int row = wn * 32 + np * 16 + rsel;
                uint32_t off = (uint32_t)(row * 128 + ks * 32 + hsel * 16);
                uint32_t sw  = off ^ ((off >> 3) & 0x70);
                uint32_t q0, q1, q2, q3;
                ldsm_x4(q0, q1, q2, q3, bS + sw);
                bf[2 * np][0]     = q0; bf[2 * np][1]     = q2;
                bf[2 * np + 1][0] = q1; bf[2 * np + 1][1] = q3;
            }
            #pragma unroll
            for (int mt = 0; mt < 4; mt++)
                #pragma unroll
                for (int nt = 0; nt < 4; nt++)
                    mma_f16(acc[mt][nt], af[mt], bf[nt]);
        }
        __syncthreads();
    }

    // epilogue: acc + bias -> C (fp32)
    const int cx = (lane & 3) * 2;
    const int cy = lane >> 2;
    #pragma unroll
    for (int nt = 0; nt < 4; nt++) {
        const int c0 = bn + wn * 32 + nt * 8 + cx;
        const float bv0 = bias[c0];
        const float bv1 = bias[c0 + 1];
        #pragma unroll
        for (int mt = 0; mt < 4; mt++) {
            const int r0 = bm + wm * 64 + mt * 16 + cy;
            *(float2*)(C + (size_t)r0 * N + c0)       = make_float2(acc[mt][nt][0] + bv0, acc[mt][nt][1] + bv1);
            *(float2*)(C + (size_t)(r0 + 8) * N + c0) = make_float2(acc[mt][nt][2] + bv0, acc[mt][nt][3] + bv1);
        }
    }
}

// ---------------- attention: sliding-window causal GQA with sink ----------------
// block 512 = 4 q-heads x 64 queries x 2 dim-halves; fp16 output.
__global__ __launch_bounds__(512) void attn_kernel(
    const float* __restrict__ qkv, const float* __restrict__ sinks,
    __half* __restrict__ out)
{
    extern __shared__ float smem[];
    float* Ks = smem;
    float* Vs = smem + 191 * 64;

    const int qb = blockIdx.x;
    const int kv = blockIdx.y;
    const int b  = blockIdx.z;
    const int tid = threadIdx.x;

    const int qstart = qb * 64;
    const int j0 = qstart - (WIN - 1);

    for (int idx = tid; idx < 191 * 16; idx += 512) {
        int row = idx >> 4;
        int c   = (idx & 15) << 2;
        int j   = j0 + row;
        float4 kk4 = make_float4(0.f, 0.f, 0.f, 0.f);
        float4 vv4 = make_float4(0.f, 0.f, 0.f, 0.f);
        if (j >= 0) {
            const float* base = qkv + (size_t)(b * T_ + j) * QKVD;
            kk4 = *(const float4*)(base + 2048 + kv * 64 + c);
            vv4 = *(const float4*)(base + 2560 + kv * 64 + c);
        }
        *(float4*)(Ks + row * 64 + c) = kk4;
        *(float4*)(Vs + row * 64 + c) = vv4;
    }

    const int half = tid & 1;            // which 32-dim half this thread owns
    const int qi   = (tid >> 1) & 63;
    const int qh   = tid >> 7;           // 0..3
    const int h    = kv * QMULT + qh;
    const int i    = qstart + qi;
    const int dbase = half * 32;

    float qv[32];
    {
        const float* qp = qkv + (size_t)(b * T_ + i) * QKVD + h * 64 + dbase;
        #pragma unroll
        for (int d = 0; d < 32; d += 4) {
            float4 t4 = *(const float4*)(qp + d);
            qv[d] = t4.x; qv[d + 1] = t4.y; qv[d + 2] = t4.z; qv[d + 3] = t4.w;
        }
    }

    __syncthreads();

    float m = -CUDART_INF_F;
    float l = 0.0f;
    float o[32];
    #pragma unroll
    for (int d = 0; d < 32; d++) o[d] = 0.0f;

    for (int jr = 0; jr < 191; jr++) {
        int j = j0 + jr;
        // partial dot over this thread's 32 dims (computed by all lanes -> uniform flow)
        const float* kr = Ks + jr * 64 + dbase;
        float s0 = 0.f, s1 = 0.f, s2 = 0.f, s3 = 0.f;
        #pragma unroll
        for (int d = 0; d < 32; d += 4) {
            float4 k4 = *(const float4*)(kr + d);
            s0 = fmaf(qv[d + 0], k4.x, s0);
            s1 = fmaf(qv[d + 1], k4.y, s1);
            s2 = fmaf(qv[d + 2], k4.z, s2);
            s3 = fmaf(qv[d + 3], k4.w, s3);
        }
        float part = (s0 + s1) + (s2 + s3);
        float s = (part + __shfl_xor_sync(0xffffffffu, part, 1)) * SM_SCALE;

        bool valid = (jr >= qi) && (jr <= qi + (WIN - 1)) && (j >= 0);
        if (valid) {
            if (s > m) {
                float corr = __expf(m - s);
                l *= corr;
                #pragma unroll
                for (int d = 0; d < 32; d++) o[d] *= corr;
                m = s;
            }
            float p = __expf(s - m);
            l += p;
            const float* vr = Vs + jr * 64 + dbase;
            #pragma unroll
            for (int d = 0; d < 32; d += 4) {
                float4 v4 = *(const float4*)(vr + d);
                o[d + 0] = fmaf(p, v4.x, o[d + 0]);
                o[d + 1] = fmaf(p, v4.y, o[d + 1]);
                o[d + 2] = fmaf(p, v4.z, o[d + 2]);
                o[d + 3] = fmaf(p, v4.w, o[d + 3]);
            }
        }
    }

    float denom = l + __expf(sinks[h] - m);
    float inv = 1.0f / denom;
    __half2* op = (__half2*)(out + (size_t)(b * T_ + i) * DM + h * 64 + dbase);
    #pragma unroll
    for (int d = 0; d < 32; d += 2)
        op[d >> 1] = __floats2half2_rn(o[d] * inv, o[d + 1] * inv);
}

// ---------------- launch ----------------
extern "C" void kernel_launch(void* const* d_in, const int* in_sizes, int n_in,
                              void* d_out, int out_size) {
    const float* x      = (const float*)d_in[0];
    const float* qkv_w  = (const float*)d_in[1];
    const float* qkv_b  = (const float*)d_in[2];
    const float* out_w  = (const float*)d_in[3];
    const float* out_b  = (const float*)d_in[4];
    const float* sinks  = (const float*)d_in[5];
    float* out = (float*)d_out;

    float *qkv, *cosp, *sinp;
    __half *xh, *qwh, *owh, *attnh;
    cudaGetSymbolAddress((void**)&qkv,   g_qkv);
    cudaGetSymbolAddress((void**)&xh,    g_xh);
    cudaGetSymbolAddress((void**)&qwh,   g_qwh);
    cudaGetSymbolAddress((void**)&owh,   g_owh);
    cudaGetSymbolAddress((void**)&attnh, g_attnh);
    cudaGetSymbolAddress((void**)&cosp,  g_cos);
    cudaGetSymbolAddress((void**)&sinp,  g_sin);

    const int gemmSmem = 2 * STAGE_BYTES + 1024;   // 66560
    cudaFuncSetAttribute(gemm_f16_nt_bias, cudaFuncAttributeMaxDynamicSharedMemorySize, gemmSmem);
    cudaFuncSetAttribute(attn_kernel, cudaFuncAttributeMaxDynamicSharedMemorySize, 98304);

    // 1. rope tables
    rope_table_kernel<<<T_, 32>>>(cosp, sinp);

    // 2. fp16 conversion passes
    {
        int n4x = NTOK * DM / 4;
        f16_convert_kernel<<<(n4x + 255) / 256, 256>>>(x, xh, n4x);
        int n4q = QKVD * DM / 4;
        f16_convert_kernel<<<(n4q + 255) / 256, 256>>>(qkv_w, qwh, n4q);
        int n4o = DM * DM / 4;
        f16_convert_kernel<<<(n4o + 255) / 256, 256>>>(out_w, owh, n4o);
    }

    // 3. QKV projection: [4096,3072] = x @ qkv_w^T + b   (fp16 mma)
    {
        dim3 grid(QKVD / BN, NTOK / BM);   // (24, 32)
        gemm_f16_nt_bias<<<grid, 256, gemmSmem>>>(xh, qwh, qkv_b, qkv, NTOK, QKVD, DM);
    }

    // 4. rope on q + k heads (in place, fp32)
    {
        int total = NTOK * 40 * 32;
        rope_apply_kernel<<<(total + 255) / 256, 256>>>(qkv, cosp, sinp);
    }

    // 5. attention (fp16 output)
    {
        dim3 grid(T_ / 64, NKV, B_);
        attn_kernel<<<grid, 512, 191 * 64 * 2 * sizeof(float)>>>(qkv, sinks, attnh);
    }

    // 6. output projection: [4096,2048] = attn @ out_w^T + b  (fp16 mma)
    {
        dim3 grid(DM / BN, NTOK / BM);     // (16, 32)
        gemm_f16_nt_bias<<<grid, 256, gemmSmem>>>(attnh, owh, out_b, out, NTOK, DM, DM);
    }
}

// round 6
// speedup vs baseline: 3.3723x; 1.1972x over previous
#include <cuda_runtime.h>
#include <cuda_fp16.h>
#include <math.h>
#include <math_constants.h>
#include <stdint.h>

// ---------------- problem constants ----------------
#define B_    4
#define T_    1024
#define DM    2048
#define HD    64
#define NH    32
#define NKV   8
#define QMULT 4
#define WIN   128
#define QKVD  3072           // 64*(32+16)
#define SM_SCALE 0.125f      // 1/sqrt(64)
#define NTOK  (B_*T_)        // 4096

// ---------------- scratch (no allocs allowed) ----------------
__device__ float  g_qkv  [NTOK * QKVD];  // 50.3 MB  qkv projection output (fp32)
__device__ __half g_xh   [NTOK * DM];    // 16.8 MB  x -> fp16
__device__ __half g_qwh  [QKVD * DM];    // 12.6 MB  qkv_w -> fp16
__device__ __half g_owh  [DM * DM];      //  8.4 MB  out_w -> fp16
__device__ __half g_attnh[NTOK * DM];    // 16.8 MB  attn output (fp16)
__device__ float  g_cos  [T_ * 32];
__device__ float  g_sin  [T_ * 32];

// ---------------- PTX helpers ----------------
__device__ __forceinline__ uint32_t smem_u32(const void* p) {
    uint32_t a;
    asm("{ .reg .u64 t; cvta.to.shared.u64 t, %1; cvt.u32.u64 %0, t; }" : "=r"(a) : "l"(p));
    return a;
}
__device__ __forceinline__ void cp16(uint32_t dst, const void* src) {
    asm volatile("cp.async.cg.shared.global [%0], [%1], 16;" :: "r"(dst), "l"(src));
}
__device__ __forceinline__ void ldsm_x4(uint32_t& r0, uint32_t& r1, uint32_t& r2, uint32_t& r3, uint32_t addr) {
    asm volatile("ldmatrix.sync.aligned.m8n8.x4.shared.b16 {%0,%1,%2,%3}, [%4];"
        : "=r"(r0), "=r"(r1), "=r"(r2), "=r"(r3) : "r"(addr));
}
__device__ __forceinline__ void mma_f16(float* c, const uint32_t* a, const uint32_t* b) {
    asm volatile("mma.sync.aligned.m16n8k16.row.col.f32.f16.f16.f32 "
        "{%0,%1,%2,%3}, {%4,%5,%6,%7}, {%8,%9}, {%0,%1,%2,%3};"
        : "+f"(c[0]), "+f"(c[1]), "+f"(c[2]), "+f"(c[3])
        : "r"(a[0]), "r"(a[1]), "r"(a[2]), "r"(a[3]), "r"(b[0]), "r"(b[1]));
}

// ---------------- rope tables (YaRN / NTK-by-parts) ----------------
__global__ void rope_table_kernel(float* __restrict__ cost, float* __restrict__ sint) {
    int t = blockIdx.x;
    int d = threadIdx.x;
    const double theta = 150000.0;
    const double two_pi = 6.283185307179586476925286766559;
    double freq = pow(theta, (double)d / 32.0);
    double concentration = 0.1 * log(32.0) + 1.0;
    double lt = log(theta);
    double low  = 32.0 * log(1024.0 / (32.0 * two_pi)) / lt;
    double high = 32.0 * log(1024.0 / (1.0  * two_pi)) / lt;
    double interpolation = 1.0 / (32.0 * freq);
    double extrapolation = 1.0 / freq;
    double ramp = ((double)d - low) / (high - low);
    ramp = fmin(fmax(ramp, 0.0), 1.0);
    double inv_freq = interpolation * ramp + extrapolation * (1.0 - ramp);
    double a = (double)t * inv_freq;
    cost[t * 32 + d] = (float)(cos(a) * concentration);
    sint[t * 32 + d] = (float)(sin(a) * concentration);
}

// ---------------- rope apply (q heads 0..31, k heads 32..39), in place fp32 ----------------
__global__ void rope_apply_kernel(float* __restrict__ qkv,
                                  const float* __restrict__ cost,
                                  const float* __restrict__ sint) {
    int idx = blockIdx.x * blockDim.x + threadIdx.x;
    const int total = NTOK * 40 * 32;
    if (idx >= total) return;
    int d    = idx & 31;
    int head = (idx >> 5) % 40;
    int tok  = idx / (40 * 32);
    int t    = tok & (T_ - 1);
    float c = cost[t * 32 + d];
    float s = sint[t * 32 + d];
    float* p = qkv + (size_t)tok * QKVD + head * 64;
    float x1 = p[d];
    float x2 = p[d + 32];
    p[d]      = x1 * c - x2 * s;
    p[d + 32] = x2 * c + x1 * s;
}

// ---------------- fp32 -> fp16 conversion ----------------
__global__ void f16_convert_kernel(const float* __restrict__ in, __half* __restrict__ out, int n4) {
    int i = blockIdx.x * blockDim.x + threadIdx.x;
    if (i >= n4) return;
    float4 v = ((const float4*)in)[i];
    __half2* o2 = (__half2*)out;
    o2[2 * i]     = __floats2half2_rn(v.x, v.y);
    o2[2 * i + 1] = __floats2half2_rn(v.z, v.w);
}

// ---------------- fp16 tensor-core GEMM: C[M,N] = A[M,K] @ B[N,K]^T + bias ----------------
// 128x256 CTA tile, BK=64, SW128 swizzle, 3-stage cp.async pipeline,
// 8 warps each computing 64x64 via m16n8k16, fp32 accum.
#define BM 128
#define BN 256
#define BK 64
#define A_STAGE 16384                 // 128 rows * 128B
#define B_STAGE 32768                 // 256 rows * 128B
#define STAGE_BYTES (A_STAGE + B_STAGE)
#define NSTAGE 3

__global__ __launch_bounds__(256, 1) void gemm_f16_nt_bias(
    const __half* __restrict__ A, const __half* __restrict__ Bw,
    const float* __restrict__ bias, float* __restrict__ C,
    int M, int N, int K)
{
    extern __shared__ char dsm[];
    const uint32_t dynbase = smem_u32(dsm);
    const uint32_t base    = (dynbase + 1023u) & ~1023u;

    const int tid  = threadIdx.x;
    const int lane = tid & 31;
    const int wid  = tid >> 5;
    const int wm   = wid >> 2;          // 0..1 -> m base wm*64
    const int wn   = wid & 3;           // 0..3 -> n base wn*64
    const int bm   = blockIdx.y * BM;
    const int bn   = blockIdx.x * BN;

    float acc[4][8][4];
    #pragma unroll
    for (int i = 0; i < 4; i++)
        #pragma unroll
        for (int j = 0; j < 8; j++)
            #pragma unroll
            for (int r = 0; r < 4; r++) acc[i][j][r] = 0.0f;

    const int kIter = K / BK;

    // ---- stage loader ----
    auto load_stage = [&](int buf, int t) {
        const uint32_t aS = base + buf * STAGE_BYTES;
        const uint32_t bS = aS + A_STAGE;
        const __half* Ab = A  + (size_t)bm * K + (size_t)t * BK;
        const __half* Bb = Bw + (size_t)bn * K + (size_t)t * BK;
        // A: 128 rows x 8 chunks = 1024 chunks
        #pragma unroll
        for (int j = 0; j < 4; j++) {
            int f = tid + 256 * j;
            int r = f >> 3, c = f & 7;
            uint32_t off = (uint32_t)(r * 128 + c * 16);
            uint32_t sw  = off ^ ((off >> 3) & 0x70);
            cp16(aS + sw, Ab + (size_t)r * K + c * 8);
        }
        // B: 256 rows x 8 chunks = 2048 chunks
        #pragma unroll
        for (int j = 0; j < 8; j++) {
            int f = tid + 256 * j;
            int r = f >> 3, c = f & 7;
            uint32_t off = (uint32_t)(r * 128 + c * 16);
            uint32_t sw  = off ^ ((off >> 3) & 0x70);
            cp16(bS + sw, Bb + (size_t)r * K + c * 8);
        }
    };

    load_stage(0, 0);
    asm volatile("cp.async.commit_group;");
    load_stage(1, 1);
    asm volatile("cp.async.commit_group;");

    const int rsel = lane & 15;
    const int hsel = (lane >> 4) & 1;

    for (int t = 0; t < kIter; t++) {
        asm volatile("cp.async.wait_group 1;");
        __syncthreads();

        // issue next prefetch first so it overlaps the MMA block
        if (t + 2 < kIter) load_stage((t + 2) % NSTAGE, t + 2);
        asm volatile("cp.async.commit_group;");

        const uint32_t aS = base + (t % NSTAGE) * STAGE_BYTES;
        const uint32_t bS = aS + A_STAGE;

        #pragma unroll
        for (int ks = 0; ks < 4; ks++) {
            uint32_t af[4][4];
            #pragma unroll
            for (int mt = 0; mt < 4; mt++) {
                int row = wm * 64 + mt * 16 + rsel;
                uint32_t off = (uint32_t)(row * 128 + ks * 32 + hsel * 16);
                uint32_t sw  = off ^ ((off >> 3) & 0x70);
                ldsm_x4(af[mt][0], af[mt][1], af[mt][2], af[mt][3], aS + sw);
            }
            uint32_t bf[8][2];
            #pragma unroll
            for (int np = 0; np < 4; np++) {
                int row = wn * 64 + np * 16 + rsel;
                uint32_t off = (uint32_t)(row * 128 + ks * 32 + hsel * 16);
                uint32_t sw  = off ^ ((off >> 3) & 0x70);
                uint32_t q0, q1, q2, q3;
                ldsm_x4(q0, q1, q2, q3, bS + sw);
                bf[2 * np][0]     = q0; bf[2 * np][1]     = q2;
                bf[2 * np + 1][0] = q1; bf[2 * np + 1][1] = q3;
            }
            #pragma unroll
            for (int mt = 0; mt < 4; mt++)
                #pragma unroll
                for (int nt = 0; nt < 8; nt++)
                    mma_f16(acc[mt][nt], af[mt], bf[nt]);
        }
        __syncthreads();
    }

    // epilogue: acc + bias -> C (fp32)
    const int cx = (lane & 3) * 2;
    const int cy = lane >> 2;
    #pragma unroll
    for (int nt = 0; nt < 8; nt++) {
        const int c0 = bn + wn * 64 + nt * 8 + cx;
        const float bv0 = bias[c0];
        const float bv1 = bias[c0 + 1];
        #pragma unroll
        for (int mt = 0; mt < 4; mt++) {
            const int r0 = bm + wm * 64 + mt * 16 + cy;
            *(float2*)(C + (size_t)r0 * N + c0)       = make_float2(acc[mt][nt][0] + bv0, acc[mt][nt][1] + bv1);
            *(float2*)(C + (size_t)(r0 + 8) * N + c0) = make_float2(acc[mt][nt][2] + bv0, acc[mt][nt][3] + bv1);
        }
    }
}

// ---------------- attention: sliding-window causal GQA with sink ----------------
// block 512 = 4 q-heads x 64 queries x 2 dim-halves; warp-local 143-iter window.
__global__ __launch_bounds__(512) void attn_kernel(
    const float* __restrict__ qkv, const float* __restrict__ sinks,
    __half* __restrict__ out)
{
    extern __shared__ float smem[];
    float* Ks = smem;
    float* Vs = smem + 191 * 64;

    const int qb = blockIdx.x;
    const int kv = blockIdx.y;
    const int b  = blockIdx.z;
    const int tid = threadIdx.x;

    const int qstart = qb * 64;
    const int j0 = qstart - (WIN - 1);

    for (int idx = tid; idx < 191 * 16; idx += 512) {
        int row = idx >> 4;
        int c   = (idx & 15) << 2;
        int j   = j0 + row;
        float4 kk4 = make_float4(0.f, 0.f, 0.f, 0.f);
        float4 vv4 = make_float4(0.f, 0.f, 0.f, 0.f);
        if (j >= 0) {
            const float* base = qkv + (size_t)(b * T_ + j) * QKVD;
            kk4 = *(const float4*)(base + 2048 + kv * 64 + c);
            vv4 = *(const float4*)(base + 2560 + kv * 64 + c);
        }
        *(float4*)(Ks + row * 64 + c) = kk4;
        *(float4*)(Vs + row * 64 + c) = vv4;
    }

    const int half = tid & 1;            // which 32-dim half this thread owns
    const int qi   = (tid >> 1) & 63;
    const int qh   = tid >> 7;           // 0..3
    const int h    = kv * QMULT + qh;
    const int i    = qstart + qi;
    const int dbase = half * 32;
    const int wq0  = ((tid >> 5) & 3) * 16;   // warp's base query within block

    float qv[32];
    {
        const float* qp = qkv + (size_t)(b * T_ + i) * QKVD + h * 64 + dbase;
        #pragma unroll
        for (int d = 0; d < 32; d += 4) {
            float4 t4 = *(const float4*)(qp + d);
            qv[d] = t4.x; qv[d + 1] = t4.y; qv[d + 2] = t4.z; qv[d + 3] = t4.w;
        }
    }

    __syncthreads();

    float m = -CUDART_INF_F;
    float l = 0.0f;
    float o[32];
    #pragma unroll
    for (int d = 0; d < 32; d++) o[d] = 0.0f;

    // warp covers queries [wq0, wq0+15] -> union of valid keys = [wq0, wq0+142]
    for (int w = 0; w < 143; w++) {
        int jr = wq0 + w;
        int j  = j0 + jr;
        const float* kr = Ks + jr * 64 + dbase;
        float s0 = 0.f, s1 = 0.f, s2 = 0.f, s3 = 0.f;
        #pragma unroll
        for (int d = 0; d < 32; d += 4) {
            float4 k4 = *(const float4*)(kr + d);
            s0 = fmaf(qv[d + 0], k4.x, s0);
            s1 = fmaf(qv[d + 1], k4.y, s1);
            s2 = fmaf(qv[d + 2], k4.z, s2);
            s3 = fmaf(qv[d + 3], k4.w, s3);
        }
        float part = (s0 + s1) + (s2 + s3);
        float s = (part + __shfl_xor_sync(0xffffffffu, part, 1)) * SM_SCALE;

        bool valid = (jr >= qi) && (jr <= qi + (WIN - 1)) && (j >= 0);
        if (valid) {
            if (s > m) {
                float corr = __expf(m - s);
                l *= corr;
                #pragma unroll
                for (int d = 0; d < 32; d++) o[d] *= corr;
                m = s;
            }
            float p = __expf(s - m);
            l += p;
            const float* vr = Vs + jr * 64 + dbase;
            #pragma unroll
            for (int d = 0; d < 32; d += 4) {
                float4 v4 = *(const float4*)(vr + d);
                o[d + 0] = fmaf(p, v4.x, o[d + 0]);
                o[d + 1] = fmaf(p, v4.y, o[d + 1]);
                o[d + 2] = fmaf(p, v4.z, o[d + 2]);
                o[d + 3] = fmaf(p, v4.w, o[d + 3]);
            }
        }
    }

    float denom = l + __expf(sinks[h] - m);
    float inv = 1.0f / denom;
    __half2* op = (__half2*)(out + (size_t)(b * T_ + i) * DM + h * 64 + dbase);
    #pragma unroll
    for (int d = 0; d < 32; d += 2)
        op[d >> 1] = __floats2half2_rn(o[d] * inv, o[d + 1] * inv);
}

// ---------------- launch ----------------
extern "C" void kernel_launch(void* const* d_in, const int* in_sizes, int n_in,
                              void* d_out, int out_size) {
    const float* x      = (const float*)d_in[0];
    const float* qkv_w  = (const float*)d_in[1];
    const float* qkv_b  = (const float*)d_in[2];
    const float* out_w  = (const float*)d_in[3];
    const float* out_b  = (const float*)d_in[4];
    const float* sinks  = (const float*)d_in[5];
    float* out = (float*)d_out;

    float *qkv, *cosp, *sinp;
    __half *xh, *qwh, *owh, *attnh;
    cudaGetSymbolAddress((void**)&qkv,   g_qkv);
    cudaGetSymbolAddress((void**)&xh,    g_xh);
    cudaGetSymbolAddress((void**)&qwh,   g_qwh);
    cudaGetSymbolAddress((void**)&owh,   g_owh);
    cudaGetSymbolAddress((void**)&attnh, g_attnh);
    cudaGetSymbolAddress((void**)&cosp,  g_cos);
    cudaGetSymbolAddress((void**)&sinp,  g_sin);

    const int gemmSmem = NSTAGE * STAGE_BYTES + 1024;   // 148480
    cudaFuncSetAttribute(gemm_f16_nt_bias, cudaFuncAttributeMaxDynamicSharedMemorySize, gemmSmem);
    cudaFuncSetAttribute(attn_kernel, cudaFuncAttributeMaxDynamicSharedMemorySize, 98304);

    // 1. rope tables
    rope_table_kernel<<<T_, 32>>>(cosp, sinp);

    // 2. fp16 conversion passes
    {
        int n4x = NTOK * DM / 4;
        f16_convert_kernel<<<(n4x + 255) / 256, 256>>>(x, xh, n4x);
        int n4q = QKVD * DM / 4;
        f16_convert_kernel<<<(n4q + 255) / 256, 256>>>(qkv_w, qwh, n4q);
        int n4o = DM * DM / 4;
        f16_convert_kernel<<<(n4o + 255) / 256, 256>>>(out_w, owh, n4o);
    }

    // 3. QKV projection: [4096,3072] = x @ qkv_w^T + b   (fp16 mma)
    {
        dim3 grid(QKVD / BN, NTOK / BM);   // (12, 32)
        gemm_f16_nt_bias<<<grid, 256, gemmSmem>>>(xh, qwh, qkv_b, qkv, NTOK, QKVD, DM);
    }

    // 4. rope on q + k heads (in place, fp32)
    {
        int total = NTOK * 40 * 32;
        rope_apply_kernel<<<(total + 255) / 256, 256>>>(qkv, cosp, sinp);
    }

    // 5. attention (fp16 output)
    {
        dim3 grid(T_ / 64, NKV, B_);
        attn_kernel<<<grid, 512, 191 * 64 * 2 * sizeof(float)>>>(qkv, sinks, attnh);
    }

    // 6. output projection: [4096,2048] = attn @ out_w^T + b  (fp16 mma)
    {
        dim3 grid(DM / BN, NTOK / BM);     // (8, 32)
        gemm_f16_nt_bias<<<grid, 256, gemmSmem>>>(attnh, owh, out_b, out, NTOK, DM, DM);
    }
}

// round 7
// speedup vs baseline: 3.4687x; 1.0286x over previous
#include <cuda_runtime.h>
#include <cuda_fp16.h>
#include <math.h>
#include <math_constants.h>
#include <stdint.h>

// ---------------- problem constants ----------------
#define B_    4
#define T_    1024
#define DM    2048
#define HD    64
#define NH    32
#define NKV   8
#define QMULT 4
#define WIN   128
#define QKVD  3072           // 64*(32+16)
#define SM_SCALE 0.125f      // 1/sqrt(64)
#define NTOK  (B_*T_)        // 4096

// ---------------- scratch (no allocs allowed) ----------------
__device__ float  g_qkv  [NTOK * QKVD];  // 50.3 MB  qkv projection output (fp32)
__device__ __half g_xh   [NTOK * DM];    // 16.8 MB  x -> fp16
__device__ __half g_qwh  [QKVD * DM];    // 12.6 MB  qkv_w -> fp16
__device__ __half g_owh  [DM * DM];      //  8.4 MB  out_w -> fp16
__device__ __half g_attnh[NTOK * DM];    // 16.8 MB  attn output (fp16)
__device__ float  g_cos  [T_ * 32];
__device__ float  g_sin  [T_ * 32];

// ---------------- PTX helpers ----------------
__device__ __forceinline__ uint32_t smem_u32(const void* p) {
    uint32_t a;
    asm("{ .reg .u64 t; cvta.to.shared.u64 t, %1; cvt.u32.u64 %0, t; }" : "=r"(a) : "l"(p));
    return a;
}
__device__ __forceinline__ void cp16(uint32_t dst, const void* src) {
    asm volatile("cp.async.cg.shared.global [%0], [%1], 16;" :: "r"(dst), "l"(src));
}
__device__ __forceinline__ void ldsm_x4(uint32_t& r0, uint32_t& r1, uint32_t& r2, uint32_t& r3, uint32_t addr) {
    asm volatile("ldmatrix.sync.aligned.m8n8.x4.shared.b16 {%0,%1,%2,%3}, [%4];"
        : "=r"(r0), "=r"(r1), "=r"(r2), "=r"(r3) : "r"(addr));
}
__device__ __forceinline__ void mma_f16(float* c, const uint32_t* a, const uint32_t* b) {
    asm volatile("mma.sync.aligned.m16n8k16.row.col.f32.f16.f16.f32 "
        "{%0,%1,%2,%3}, {%4,%5,%6,%7}, {%8,%9}, {%0,%1,%2,%3};"
        : "+f"(c[0]), "+f"(c[1]), "+f"(c[2]), "+f"(c[3])
        : "r"(a[0]), "r"(a[1]), "r"(a[2]), "r"(a[3]), "r"(b[0]), "r"(b[1]));
}

// ---------------- rope tables (YaRN / NTK-by-parts) ----------------
__global__ void rope_table_kernel(float* __restrict__ cost, float* __restrict__ sint) {
    int t = blockIdx.x;
    int d = threadIdx.x;
    const double theta = 150000.0;
    const double two_pi = 6.283185307179586476925286766559;
    double freq = pow(theta, (double)d / 32.0);
    double concentration = 0.1 * log(32.0) + 1.0;
    double lt = log(theta);
    double low  = 32.0 * log(1024.0 / (32.0 * two_pi)) / lt;
    double high = 32.0 * log(1024.0 / (1.0  * two_pi)) / lt;
    double interpolation = 1.0 / (32.0 * freq);
    double extrapolation = 1.0 / freq;
    double ramp = ((double)d - low) / (high - low);
    ramp = fmin(fmax(ramp, 0.0), 1.0);
    double inv_freq = interpolation * ramp + extrapolation * (1.0 - ramp);
    double a = (double)t * inv_freq;
    cost[t * 32 + d] = (float)(cos(a) * concentration);
    sint[t * 32 + d] = (float)(sin(a) * concentration);
}

// ---------------- rope apply (q heads 0..31, k heads 32..39), in place fp32 ----------------
__global__ void rope_apply_kernel(float* __restrict__ qkv,
                                  const float* __restrict__ cost,
                                  const float* __restrict__ sint) {
    int idx = blockIdx.x * blockDim.x + threadIdx.x;
    const int total = NTOK * 40 * 32;
    if (idx >= total) return;
    int d    = idx & 31;
    int head = (idx >> 5) % 40;
    int tok  = idx / (40 * 32);
    int t    = tok & (T_ - 1);
    float c = cost[t * 32 + d];
    float s = sint[t * 32 + d];
    float* p = qkv + (size_t)tok * QKVD + head * 64;
    float x1 = p[d];
    float x2 = p[d + 32];
    p[d]      = x1 * c - x2 * s;
    p[d + 32] = x2 * c + x1 * s;
}

// ---------------- fp32 -> fp16 conversion ----------------
__global__ void f16_convert_kernel(const float* __restrict__ in, __half* __restrict__ out, int n4) {
    int i = blockIdx.x * blockDim.x + threadIdx.x;
    if (i >= n4) return;
    float4 v = ((const float4*)in)[i];
    __half2* o2 = (__half2*)out;
    o2[2 * i]     = __floats2half2_rn(v.x, v.y);
    o2[2 * i + 1] = __floats2half2_rn(v.z, v.w);
}

// ---------------- fp16 tensor-core GEMM: C[M,N] = A[M,K] @ B[N,K]^T + bias ----------------
// 128x256 CTA tile, BK=64, SW128 swizzle, 4-stage cp.async pipeline (wait_group 2),
// single syncthreads per K-iter, 8 warps each computing 64x64 via m16n8k16, fp32 accum.
#define BM 128
#define BN 256
#define BK 64
#define A_STAGE 16384                 // 128 rows * 128B
#define B_STAGE 32768                 // 256 rows * 128B
#define STAGE_BYTES (A_STAGE + B_STAGE)
#define NSTAGE 4

__global__ __launch_bounds__(256, 1) void gemm_f16_nt_bias(
    const __half* __restrict__ A, const __half* __restrict__ Bw,
    const float* __restrict__ bias, float* __restrict__ C,
    int M, int N, int K)
{
    extern __shared__ char dsm[];
    const uint32_t dynbase = smem_u32(dsm);
    const uint32_t base    = (dynbase + 1023u) & ~1023u;

    const int tid  = threadIdx.x;
    const int lane = tid & 31;
    const int wid  = tid >> 5;
    const int wm   = wid >> 2;          // 0..1 -> m base wm*64
    const int wn   = wid & 3;           // 0..3 -> n base wn*64
    const int bm   = blockIdx.y * BM;
    const int bn   = blockIdx.x * BN;

    float acc[4][8][4];
    #pragma unroll
    for (int i = 0; i < 4; i++)
        #pragma unroll
        for (int j = 0; j < 8; j++)
            #pragma unroll
            for (int r = 0; r < 4; r++) acc[i][j][r] = 0.0f;

    const int kIter = K / BK;

    // ---- stage loader ----
    auto load_stage = [&](int buf, int t) {
        const uint32_t aS = base + buf * STAGE_BYTES;
        const uint32_t bS = aS + A_STAGE;
        const __half* Ab = A  + (size_t)bm * K + (size_t)t * BK;
        const __half* Bb = Bw + (size_t)bn * K + (size_t)t * BK;
        // A: 128 rows x 8 chunks = 1024 chunks
        #pragma unroll
        for (int j = 0; j < 4; j++) {
            int f = tid + 256 * j;
            int r = f >> 3, c = f & 7;
            uint32_t off = (uint32_t)(r * 128 + c * 16);
            uint32_t sw  = off ^ ((off >> 3) & 0x70);
            cp16(aS + sw, Ab + (size_t)r * K + c * 8);
        }
        // B: 256 rows x 8 chunks = 2048 chunks
        #pragma unroll
        for (int j = 0; j < 8; j++) {
            int f = tid + 256 * j;
            int r = f >> 3, c = f & 7;
            uint32_t off = (uint32_t)(r * 128 + c * 16);
            uint32_t sw  = off ^ ((off >> 3) & 0x70);
            cp16(bS + sw, Bb + (size_t)r * K + c * 8);
        }
    };

    load_stage(0, 0);
    asm volatile("cp.async.commit_group;");
    load_stage(1, 1);
    asm volatile("cp.async.commit_group;");
    load_stage(2, 2);
    asm volatile("cp.async.commit_group;");

    const int rsel = lane & 15;
    const int hsel = (lane >> 4) & 1;

    for (int t = 0; t < kIter; t++) {
        asm volatile("cp.async.wait_group 2;");   // stage t complete
        __syncthreads();                           // publish + all warps done with stage (t-1)

        // prefetch stage t+3 into buffer (t+3)&3 (== (t-1)&3, safe after the barrier)
        if (t + 3 < kIter) load_stage((t + 3) & 3, t + 3);
        asm volatile("cp.async.commit_group;");

        const uint32_t aS = base + (t & 3) * STAGE_BYTES;
        const uint32_t bS = aS + A_STAGE;

        #pragma unroll
        for (int ks = 0; ks < 4; ks++) {
            uint32_t af[4][4];
            #pragma unroll
            for (int mt = 0; mt < 4; mt++) {
                int row = wm * 64 + mt * 16 + rsel;
                uint32_t off = (uint32_t)(row * 128 + ks * 32 + hsel * 16);
                uint32_t sw  = off ^ ((off >> 3) & 0x70);
                ldsm_x4(af[mt][0], af[mt][1], af[mt][2], af[mt][3], aS + sw);
            }
            uint32_t bf[8][2];
            #pragma unroll
            for (int np = 0; np < 4; np++) {
                int row = wn * 64 + np * 16 + rsel;
                uint32_t off = (uint32_t)(row * 128 + ks * 32 + hsel * 16);
                uint32_t sw  = off ^ ((off >> 3) & 0x70);
                uint32_t q0, q1, q2, q3;
                ldsm_x4(q0, q1, q2, q3, bS + sw);
                bf[2 * np][0]     = q0; bf[2 * np][1]     = q2;
                bf[2 * np + 1][0] = q1; bf[2 * np + 1][1] = q3;
            }
            #pragma unroll
            for (int mt = 0; mt < 4; mt++)
                #pragma unroll
                for (int nt = 0; nt < 8; nt++)
                    mma_f16(acc[mt][nt], af[mt], bf[nt]);
        }
        // no trailing barrier: next iteration's top barrier provides the ordering
    }

    // epilogue: acc + bias -> C (fp32)
    const int cx = (lane & 3) * 2;
    const int cy = lane >> 2;
    #pragma unroll
    for (int nt = 0; nt < 8; nt++) {
        const int c0 = bn + wn * 64 + nt * 8 + cx;
        const float bv0 = bias[c0];
        const float bv1 = bias[c0 + 1];
        #pragma unroll
        for (int mt = 0; mt < 4; mt++) {
            const int r0 = bm + wm * 64 + mt * 16 + cy;
            *(float2*)(C + (size_t)r0 * N + c0)       = make_float2(acc[mt][nt][0] + bv0, acc[mt][nt][1] + bv1);
            *(float2*)(C + (size_t)(r0 + 8) * N + c0) = make_float2(acc[mt][nt][2] + bv0, acc[mt][nt][3] + bv1);
        }
    }
}

// ---------------- attention: sliding-window causal GQA with sink ----------------
// block 512 = 4 q-heads x 64 queries x 2 dim-halves; warp-local 143-iter window.
__global__ __launch_bounds__(512) void attn_kernel(
    const float* __restrict__ qkv, const float* __restrict__ sinks,
    __half* __restrict__ out)
{
    extern __shared__ float smem[];
    float* Ks = smem;
    float* Vs = smem + 191 * 64;

    const int qb = blockIdx.x;
    const int kv = blockIdx.y;
    const int b  = blockIdx.z;
    const int tid = threadIdx.x;

    const int qstart = qb * 64;
    const int j0 = qstart - (WIN - 1);

    for (int idx = tid; idx < 191 * 16; idx += 512) {
        int row = idx >> 4;
        int c   = (idx & 15) << 2;
        int j   = j0 + row;
        float4 kk4 = make_float4(0.f, 0.f, 0.f, 0.f);
        float4 vv4 = make_float4(0.f, 0.f, 0.f, 0.f);
        if (j >= 0) {
            const float* base = qkv + (size_t)(b * T_ + j) * QKVD;
            kk4 = *(const float4*)(base + 2048 + kv * 64 + c);
            vv4 = *(const float4*)(base + 2560 + kv * 64 + c);
        }
        *(float4*)(Ks + row * 64 + c) = kk4;
        *(float4*)(Vs + row * 64 + c) = vv4;
    }

    const int half = tid & 1;            // which 32-dim half this thread owns
    const int qi   = (tid >> 1) & 63;
    const int qh   = tid >> 7;           // 0..3
    const int h    = kv * QMULT + qh;
    const int i    = qstart + qi;
    const int dbase = half * 32;
    const int wq0  = ((tid >> 5) & 3) * 16;   // warp's base query within block

    float qv[32];
    {
        const float* qp = qkv + (size_t)(b * T_ + i) * QKVD + h * 64 + dbase;
        #pragma unroll
        for (int d = 0; d < 32; d += 4) {
            float4 t4 = *(const float4*)(qp + d);
            qv[d] = t4.x; qv[d + 1] = t4.y; qv[d + 2] = t4.z; qv[d + 3] = t4.w;
        }
    }

    __syncthreads();

    float m = -CUDART_INF_F;
    float l = 0.0f;
    float o[32];
    #pragma unroll
    for (int d = 0; d < 32; d++) o[d] = 0.0f;

    // warp covers queries [wq0, wq0+15] -> union of valid keys = [wq0, wq0+142]
    for (int w = 0; w < 143; w++) {
        int jr = wq0 + w;
        int j  = j0 + jr;
        const float* kr = Ks + jr * 64 + dbase;
        float s0 = 0.f, s1 = 0.f, s2 = 0.f, s3 = 0.f;
        #pragma unroll
        for (int d = 0; d < 32; d += 4) {
            float4 k4 = *(const float4*)(kr + d);
            s0 = fmaf(qv[d + 0], k4.x, s0);
            s1 = fmaf(qv[d + 1], k4.y, s1);
            s2 = fmaf(qv[d + 2], k4.z, s2);
            s3 = fmaf(qv[d + 3], k4.w, s3);
        }
        float part = (s0 + s1) + (s2 + s3);
        float s = (part + __shfl_xor_sync(0xffffffffu, part, 1)) * SM_SCALE;

        bool valid = (jr >= qi) && (jr <= qi + (WIN - 1)) && (j >= 0);
        if (valid) {
            if (s > m) {
                float corr = __expf(m - s);
                l *= corr;
                #pragma unroll
                for (int d = 0; d < 32; d++) o[d] *= corr;
                m = s;
            }
            float p = __expf(s - m);
            l += p;
            const float* vr = Vs + jr * 64 + dbase;
            #pragma unroll
            for (int d = 0; d < 32; d += 4) {
                float4 v4 = *(const float4*)(vr + d);
                o[d + 0] = fmaf(p, v4.x, o[d + 0]);
                o[d + 1] = fmaf(p, v4.y, o[d + 1]);
                o[d + 2] = fmaf(p, v4.z, o[d + 2]);
                o[d + 3] = fmaf(p, v4.w, o[d + 3]);
            }
        }
    }

    float denom = l + __expf(sinks[h] - m);
    float inv = 1.0f / denom;
    __half2* op = (__half2*)(out + (size_t)(b * T_ + i) * DM + h * 64 + dbase);
    #pragma unroll
    for (int d = 0; d < 32; d += 2)
        op[d >> 1] = __floats2half2_rn(o[d] * inv, o[d + 1] * inv);
}

// ---------------- launch ----------------
extern "C" void kernel_launch(void* const* d_in, const int* in_sizes, int n_in,
                              void* d_out, int out_size) {
    const float* x      = (const float*)d_in[0];
    const float* qkv_w  = (const float*)d_in[1];
    const float* qkv_b  = (const float*)d_in[2];
    const float* out_w  = (const float*)d_in[3];
    const float* out_b  = (const float*)d_in[4];
    const float* sinks  = (const float*)d_in[5];
    float* out = (float*)d_out;

    float *qkv, *cosp, *sinp;
    __half *xh, *qwh, *owh, *attnh;
    cudaGetSymbolAddress((void**)&qkv,   g_qkv);
    cudaGetSymbolAddress((void**)&xh,    g_xh);
    cudaGetSymbolAddress((void**)&qwh,   g_qwh);
    cudaGetSymbolAddress((void**)&owh,   g_owh);
    cudaGetSymbolAddress((void**)&attnh, g_attnh);
    cudaGetSymbolAddress((void**)&cosp,  g_cos);
    cudaGetSymbolAddress((void**)&sinp,  g_sin);

    const int gemmSmem = NSTAGE * STAGE_BYTES + 1024;   // 197632
    cudaFuncSetAttribute(gemm_f16_nt_bias, cudaFuncAttributeMaxDynamicSharedMemorySize, gemmSmem);
    cudaFuncSetAttribute(attn_kernel, cudaFuncAttributeMaxDynamicSharedMemorySize, 98304);

    // 1. rope tables
    rope_table_kernel<<<T_, 32>>>(cosp, sinp);

    // 2. fp16 conversion passes
    {
        int n4x = NTOK * DM / 4;
        f16_convert_kernel<<<(n4x + 255) / 256, 256>>>(x, xh, n4x);
        int n4q = QKVD * DM / 4;
        f16_convert_kernel<<<(n4q + 255) / 256, 256>>>(qkv_w, qwh, n4q);
        int n4o = DM * DM / 4;
        f16_convert_kernel<<<(n4o + 255) / 256, 256>>>(out_w, owh, n4o);
    }

    // 3. QKV projection: [4096,3072] = x @ qkv_w^T + b   (fp16 mma)
    {
        dim3 grid(QKVD / BN, NTOK / BM);   // (12, 32)
        gemm_f16_nt_bias<<<grid, 256, gemmSmem>>>(xh, qwh, qkv_b, qkv, NTOK, QKVD, DM);
    }

    // 4. rope on q + k heads (in place, fp32)
    {
        int total = NTOK * 40 * 32;
        rope_apply_kernel<<<(total + 255) / 256, 256>>>(qkv, cosp, sinp);
    }

    // 5. attention (fp16 output)
    {
        dim3 grid(T_ / 64, NKV, B_);
        attn_kernel<<<grid, 512, 191 * 64 * 2 * sizeof(float)>>>(qkv, sinks, attnh);
    }

    // 6. output projection: [4096,2048] = attn @ out_w^T + b  (fp16 mma)
    {
        dim3 grid(DM / BN, NTOK / BM);     // (8, 32)
        gemm_f16_nt_bias<<<grid, 256, gemmSmem>>>(attnh, owh, out_b, out, NTOK, DM, DM);
    }
}